// round 7
// baseline (speedup 1.0000x reference)
#include <cuda_runtime.h>
#include <math.h>

#define SEQ   4096
#define LW    24
#define EMBD  300
#define CHOUT 25
#define CHE   25
#define HIDN  512
#define INPD  325      // EMB + CH_OUT
#define EMBS  336      // padded K (21 * 16) for vectorized GEMM
#define NTAG  11
#define STARTT 9
#define STOPT  10
#define NEGV  -10000.0f
#define NGATE 2048     // 4*HIDN
#define SENT  0x7FC00ABCu   // NaN payload sentinel: h in (-1,1) can never be NaN
#define HROW  2048     // floats per timestep row of g_h2 (128 granules * 16)

typedef unsigned long long u64;

// ---------------- static device scratch (no allocs allowed) ----------------
__device__ float g_emb[SEQ * EMBS];             // 5.5 MB  [t][k], cols >=325 zero
__device__ float g_W[2][NGATE * EMBS];          // 5.5 MB  padded Wih
__device__ float g_G[2][SEQ * NGATE];           // 64 MB   Wih@x + bih + bhh
__device__ float g_h2[2][SEQ * HROW];           // 64 MB   spread hidden states:
                                                //   h[t][4g..4g+3] at floats t*HROW + g*16
__device__ float g_feats[SEQ * 16];             // padded [t][tag]

// ---------------- helpers ----------------
__device__ __forceinline__ float4 ld_rlx4(const float4* p) {
    float4 v;
    asm volatile("ld.relaxed.gpu.global.v4.f32 {%0,%1,%2,%3}, [%4];"
                 : "=f"(v.x), "=f"(v.y), "=f"(v.z), "=f"(v.w) : "l"(p));
    return v;
}
__device__ __forceinline__ void st_rlx(float* p, float v) {
    asm volatile("st.relaxed.gpu.global.f32 [%0], %1;" :: "l"(p), "f"(v));
}
__device__ __forceinline__ u64 fma2(u64 a, u64 b, u64 c) {
    u64 d;
    asm("fma.rn.f32x2 %0, %1, %2, %3;" : "=l"(d) : "l"(a), "l"(b), "l"(c));
    return d;
}
__device__ __forceinline__ u64 add2(u64 a, u64 b) {
    u64 d;
    asm("add.rn.f32x2 %0, %1, %2;" : "=l"(d) : "l"(a), "l"(b));
    return d;
}
__device__ __forceinline__ void upk2(u64 v, float& lo, float& hi) {
    asm("mov.b64 {%0,%1}, %2;" : "=f"(lo), "=f"(hi) : "l"(v));
}
__device__ __forceinline__ float sigf(float x) {
    return __fdividef(1.0f, 1.0f + __expf(-x));
}
__device__ __forceinline__ float tanh_fast(float x) {
    return __fdividef(2.0f, 1.0f + __expf(-2.0f * x)) - 1.0f;
}

// ---------------- poison hidden-state buffer (data-as-flag protocol) --------
__global__ void poison_kernel() {
    size_t i = (size_t)blockIdx.x * blockDim.x + threadIdx.x;  // over float4s
    float s = __uint_as_float(SENT);
    ((float4*)&g_h2[0][0])[i] = make_float4(s, s, s, s);
}

// ---------------- pad Wih into g_W (zero-filled K padding) ------------------
__global__ void padw_kernel(const float* __restrict__ Wf,
                            const float* __restrict__ Wb) {
    int i = blockIdx.x * blockDim.x + threadIdx.x;
    if (i >= NGATE * EMBS) return;
    int r = i / EMBS, k = i - r * EMBS;
    g_W[0][i] = (k < INPD) ? Wf[r * INPD + k] : 0.0f;
    g_W[1][i] = (k < INPD) ? Wb[r * INPD + k] : 0.0f;
}

// ---------------- char CNN + word-embedding gather --------------------------
__global__ void embed_kernel(const int* __restrict__ sentence,
                             const int* __restrict__ chars,
                             const float* __restrict__ word_emb,
                             const float* __restrict__ char_emb,
                             const float* __restrict__ conv_w,
                             const float* __restrict__ conv_b) {
    int s = blockIdx.x;
    int tid = threadIdx.x;
    __shared__ float ce[LW][CHE];
    __shared__ float co[CHOUT][26];
    __shared__ int   cidx[LW];

    if (tid < LW) cidx[tid] = chars[s * LW + tid];
    __syncthreads();
    for (int idx = tid; idx < LW * CHE; idx += blockDim.x) {
        int r = idx / CHE, e = idx % CHE;
        ce[r][e] = char_emb[cidx[r] * CHE + e];
    }
    __syncthreads();
    for (int idx = tid; idx < CHOUT * 26; idx += blockDim.x) {
        int o = idx / 26, p = idx % 26;
        float sum = 0.0f;
        #pragma unroll
        for (int kh = 0; kh < 3; kh++) {
            int r = p - 2 + kh;
            if (r >= 0 && r < LW) {
                const float* w = conv_w + (o * 3 + kh) * CHE;
                float ss = 0.0f;
                #pragma unroll
                for (int e = 0; e < CHE; e++) ss += ce[r][e] * w[e];
                sum += ss;
            }
        }
        co[o][p] = sum;
    }
    __syncthreads();
    if (tid < CHOUT) {
        float m = -3.4e38f;
        #pragma unroll
        for (int p = 0; p < 26; p++) m = fmaxf(m, co[tid][p]);
        g_emb[s * EMBS + EMBD + tid] = m + conv_b[tid];
    }
    if (tid < EMBS - INPD) g_emb[s * EMBS + INPD + tid] = 0.0f;  // zero K pad
    int wi = sentence[s];
    const float4* src = (const float4*)(word_emb + (size_t)wi * EMBD);
    float4* dst = (float4*)(g_emb + (size_t)s * EMBS);
    for (int i = tid; i < EMBD / 4; i += blockDim.x) dst[i] = src[i];
}

// ---------------- G = emb @ Wih^T + (bih + bhh) -----------------------------
// 64x64 tile, 256 threads, 4x4 microtile, KC=16, float4 global loads from
// padded buffers (K=336, pad cols are zero so no masking needed).
__global__ __launch_bounds__(256) void gemm_kernel(
    const float* __restrict__ bihf, const float* __restrict__ bhhf,
    const float* __restrict__ bihb, const float* __restrict__ bhhb) {
    int dir = blockIdx.z;
    const float* Wp = g_W[dir];
    const float* bih = dir ? bihb : bihf;
    const float* bhh = dir ? bhhb : bhhf;
    int bm = blockIdx.y * 64;
    int bn = blockIdx.x * 64;
    int tid = threadIdx.x;
    int tx = tid & 15, ty = tid >> 4;
    int lm = tid >> 2, lk = (tid & 3) * 4;   // load map: row lm, k-offset lk

    __shared__ __align__(16) float As[16][68];
    __shared__ __align__(16) float Bs[16][68];

    float acc[4][4] = {};
    for (int k0 = 0; k0 < EMBS; k0 += 16) {
        float4 av = *(const float4*)(g_emb + (size_t)(bm + lm) * EMBS + k0 + lk);
        float4 bv = *(const float4*)(Wp + (size_t)(bn + lm) * EMBS + k0 + lk);
        As[lk + 0][lm] = av.x; As[lk + 1][lm] = av.y;
        As[lk + 2][lm] = av.z; As[lk + 3][lm] = av.w;
        Bs[lk + 0][lm] = bv.x; Bs[lk + 1][lm] = bv.y;
        Bs[lk + 2][lm] = bv.z; Bs[lk + 3][lm] = bv.w;
        __syncthreads();
        #pragma unroll
        for (int kk = 0; kk < 16; kk++) {
            float4 a = *(const float4*)&As[kk][ty * 4];
            float4 b = *(const float4*)&Bs[kk][tx * 4];
            float av4[4] = {a.x, a.y, a.z, a.w};
            float bv4[4] = {b.x, b.y, b.z, b.w};
            #pragma unroll
            for (int i = 0; i < 4; i++)
                #pragma unroll
                for (int j = 0; j < 4; j++) acc[i][j] += av4[i] * bv4[j];
        }
        __syncthreads();
    }
    float* Gp = g_G[dir];
    #pragma unroll
    for (int i = 0; i < 4; i++) {
        int t = bm + ty * 4 + i;
        #pragma unroll
        for (int j = 0; j < 4; j++) {
            int n = bn + tx * 4 + j;
            Gp[(size_t)t * NGATE + n] = acc[i][j] + bih[n] + bhh[n];
        }
    }
}

// ---------------- persistent BiLSTM recurrence -------------------------------
// R6 structure EXACTLY, except h lives in the spread layout g_h2: granule g
// (h[4g..4g+3]) occupies its own 64B segment at float offset t*HROW + g*16.
// This fans the per-step poll traffic from 16 L2 lines out to 128 lines,
// de-saturating the LTS slices so producer stores become visible promptly.
__global__ __launch_bounds__(256, 1) void lstm_kernel(
    const float* __restrict__ Whhf, const float* __restrict__ Whhb) {
    int dir = blockIdx.x >> 6;
    int b = blockIdx.x & 63;
    int tid = threadIdx.x;
    int lr = tid >> 3;     // local gate row 0..31
    int cg = tid & 7;      // column group (64 cols each)
    int gate = lr >> 3, jj = lr & 7;
    int grow = gate * HIDN + b * 8 + jj;
    const float* Whh = dir ? Whhb : Whhf;

    // 64 weights per thread in registers for the whole sequence
    ulonglong2 wgt[16];
    {
        const ulonglong2* wsrc = (const ulonglong2*)(Whh + (size_t)grow * HIDN + cg * 64);
        #pragma unroll
        for (int q = 0; q < 16; q++) wgt[q] = wsrc[q];
    }

    __shared__ float4 hs4[8 * 17];   // swizzled h_prev
    __shared__ float  gsum[32];

    const float* Gp = g_G[dir];
    float* hp = g_h2[dir];
    float cstate = 0.0f;
    float gn0 = 0.f, gn1 = 0.f, gn2 = 0.f, gn3 = 0.f;

    // prefetch G for step 0
    if (tid < 8) {
        int t0 = dir ? (SEQ - 1) : 0;
        const float* gr = Gp + (size_t)t0 * NGATE + b * 8 + tid;
        gn0 = gr[0]; gn1 = gr[512]; gn2 = gr[1024]; gn3 = gr[1536];
    }

    for (int s = 0; s < SEQ; s++) {
        int t = dir ? (SEQ - 1 - s) : s;
        float gi = gn0, gf = gn1, gg = gn2, go = gn3;
        if (tid < 8 && s + 1 < SEQ) {
            int tn = dir ? (t - 1) : (t + 1);
            const float* gr = Gp + (size_t)tn * NGATE + b * 8 + tid;
            gn0 = gr[0]; gn1 = gr[512]; gn2 = gr[1024]; gn3 = gr[1536];
        }

        if (s > 0) {
            int pt = dir ? (t + 1) : (t - 1);
            if (tid < 128) {
                // granule tid in its own 64B segment
                const float4* src = (const float4*)(hp + (size_t)pt * HROW + tid * 16);
                float4 v;
                do {
                    v = ld_rlx4(src);
                } while (__float_as_uint(v.x) == SENT || __float_as_uint(v.y) == SENT ||
                         __float_as_uint(v.z) == SENT || __float_as_uint(v.w) == SENT);
                hs4[(tid >> 4) * 17 + (tid & 15)] = v;
            }
        } else {
            if (tid < 136) hs4[tid] = make_float4(0.f, 0.f, 0.f, 0.f);
        }
        __syncthreads();

        // partial dot: 64 columns per thread via packed f32x2 FMAs
        const ulonglong2* hrow = (const ulonglong2*)(hs4 + cg * 17);
        u64 a0 = 0ULL, a1 = 0ULL, a2 = 0ULL, a3 = 0ULL;
        #pragma unroll
        for (int q = 0; q < 16; q += 2) {
            ulonglong2 h0 = hrow[q];
            ulonglong2 h1 = hrow[q + 1];
            a0 = fma2(wgt[q].x, h0.x, a0);
            a1 = fma2(wgt[q].y, h0.y, a1);
            a2 = fma2(wgt[q + 1].x, h1.x, a2);
            a3 = fma2(wgt[q + 1].y, h1.y, a3);
        }
        float lo, hi;
        upk2(add2(add2(a0, a1), add2(a2, a3)), lo, hi);
        float acc = lo + hi;
        acc += __shfl_xor_sync(0xffffffffu, acc, 4);
        acc += __shfl_xor_sync(0xffffffffu, acc, 2);
        acc += __shfl_xor_sync(0xffffffffu, acc, 1);
        if (cg == 0) gsum[lr] = acc;
        __syncthreads();

        // gates: single warp, lanes 0..7
        if (tid < 8) {
            float vi = sigf(gi + gsum[tid]);
            float vf = sigf(gf + gsum[8 + tid]);
            float vg = tanh_fast(gg + gsum[16 + tid]);
            float vo = sigf(go + gsum[24 + tid]);
            cstate = vf * cstate + vi * vg;
            float h = vo * tanh_fast(cstate);
            // lane l -> granule 2b+(l>>2), word l&3: lanes 0-3 and 4-7 each
            // form one 16B sector; single store wavefront, 2 sectors.
            st_rlx(hp + (size_t)t * HROW + (2 * b + (tid >> 2)) * 16 + (tid & 3), h);
        }
        // no trailing barrier: hs4/gsum reuse is fenced by the two barriers
        // inside the next iteration
    }
}

// ---------------- feats = [h_f ; h_b] @ h2t_w^T + h2t_b ---------------------
__global__ void feats_kernel(const float* __restrict__ h2t_w,
                             const float* __restrict__ h2t_b) {
    int t = blockIdx.x;
    int tid = threadIdx.x;
    int w = tid >> 5, lane = tid & 31;
    const float* hf = g_h2[0] + (size_t)t * HROW;
    const float* hb = g_h2[1] + (size_t)t * HROW;
    const float* wr = h2t_w + w * (2 * HIDN);
    float acc = 0.0f;
    #pragma unroll
    for (int it = 0; it < 16; it++) {
        int k = lane + it * 32;
        int ko = (k >> 2) * 16 + (k & 3);   // spread-layout offset
        acc += wr[k] * hf[ko];
        acc += wr[512 + k] * hb[ko];
    }
    #pragma unroll
    for (int o = 16; o > 0; o >>= 1) acc += __shfl_down_sync(0xffffffffu, acc, o);
    if (lane == 0) g_feats[t * 16 + w] = acc + h2t_b[w];
}

// ---------------- Viterbi + backtrack ---------------------------------------
__global__ void viterbi_kernel(const float* __restrict__ trans,
                               float* __restrict__ out, int out_size) {
    __shared__ unsigned char bp[SEQ][NTAG];   // 45 KB
    __shared__ float fbuf[32 * 16];           // 2 KB chunk of feats
    __shared__ float fvv[NTAG];
    int tid = threadIdx.x;
    int w = tid >> 5, lane = tid & 31;

    float trow[NTAG];
    float fv = NEGV;
    if (w == 0) {
        #pragma unroll
        for (int jj = 0; jj < NTAG; jj++)
            trow[jj] = (lane < NTAG) ? trans[lane * NTAG + jj] : NEGV;
        if (lane == STARTT) fv = 0.0f;
    }

    for (int c = 0; c < SEQ / 32; c++) {
        ((float4*)fbuf)[tid] = ((const float4*)(g_feats + c * 32 * 16))[tid];
        __syncthreads();
        if (w == 0) {
            #pragma unroll 4
            for (int tt = 0; tt < 32; tt++) {
                int t = c * 32 + tt;
                float featv = (lane < NTAG) ? fbuf[tt * 16 + lane] : 0.0f;
                float best = -3.4e38f; int arg = 0;
                #pragma unroll
                for (int jj = 0; jj < NTAG; jj++) {
                    float vj = __shfl_sync(0xffffffffu, fv, jj) + trow[jj];
                    if (vj > best) { best = vj; arg = jj; }
                }
                fv = best + featv;
                if (lane < NTAG) bp[t][lane] = (unsigned char)arg;
            }
        }
        __syncthreads();
    }

    if (w == 0 && lane < NTAG) fvv[lane] = fv;
    __syncthreads();

    if (tid == 0) {
        float bestv = -3.4e38f; int bi = 0;
        #pragma unroll
        for (int i = 0; i < NTAG; i++) {
            float v = fvv[i] + trans[STOPT * NTAG + i];
            if (i == STARTT || i == STOPT) v = NEGV;
            if (v > bestv) { bestv = v; bi = i; }
        }
        if (out_size > 0) out[0] = bestv;
        int tag = bi;
        for (int t = SEQ - 1; t >= 0; t--) {
            if (1 + t < out_size) out[1 + t] = (float)tag;
            tag = bp[t][tag];
        }
    }
}

// ---------------- launch --------------------------------------------------
extern "C" void kernel_launch(void* const* d_in, const int* in_sizes, int n_in,
                              void* d_out, int out_size) {
    const int*   sentence = (const int*)d_in[0];
    const int*   chars    = (const int*)d_in[1];
    const float* word_emb = (const float*)d_in[4];
    const float* char_emb = (const float*)d_in[5];
    const float* conv_w   = (const float*)d_in[6];
    const float* conv_b   = (const float*)d_in[7];
    const float* Wih_f    = (const float*)d_in[8];
    const float* Whh_f    = (const float*)d_in[9];
    const float* bih_f    = (const float*)d_in[10];
    const float* bhh_f    = (const float*)d_in[11];
    const float* Wih_b    = (const float*)d_in[12];
    const float* Whh_b    = (const float*)d_in[13];
    const float* bih_b    = (const float*)d_in[14];
    const float* bhh_b    = (const float*)d_in[15];
    const float* h2t_w    = (const float*)d_in[16];
    const float* h2t_b    = (const float*)d_in[17];
    const float* trans    = (const float*)d_in[18];
    float* out = (float*)d_out;

    // g_h2 float4 count = 2*SEQ*HROW/4 = 4,194,304 -> 16384 blocks of 256
    poison_kernel<<<16384, 256>>>();
    embed_kernel<<<SEQ, 128>>>(sentence, chars, word_emb, char_emb, conv_w, conv_b);
    padw_kernel<<<(NGATE * EMBS + 255) / 256, 256>>>(Wih_f, Wih_b);
    dim3 gg(NGATE / 64, SEQ / 64, 2);
    gemm_kernel<<<gg, 256>>>(bih_f, bhh_f, bih_b, bhh_b);
    lstm_kernel<<<128, 256>>>(Whh_f, Whh_b);
    feats_kernel<<<SEQ, 352>>>(h2t_w, h2t_b);
    viterbi_kernel<<<1, 128>>>(trans, out, out_size);
}

// round 8
// speedup vs baseline: 1.2416x; 1.2416x over previous
#include <cuda_runtime.h>
#include <math.h>

#define SEQ   4096
#define LW    24
#define EMBD  300
#define CHOUT 25
#define CHE   25
#define HIDN  512
#define INPD  325      // EMB + CH_OUT
#define EMBS  336      // padded K (21 * 16) for vectorized GEMM
#define NTAG  11
#define STARTT 9
#define STOPT  10
#define NEGV  -10000.0f
#define NGATE 2048     // 4*HIDN
#define SENT  0x7FC00ABCu   // NaN payload sentinel: h in (-1,1) can never be NaN

typedef unsigned long long u64;

// ---------------- static device scratch (no allocs allowed) ----------------
__device__ float g_emb[SEQ * EMBS];             // 5.5 MB  [t][k], cols >=325 zero
__device__ float g_W[2][NGATE * EMBS];          // 5.5 MB  padded Wih
__device__ float g_G[2][SEQ * NGATE];           // 64 MB   Wih@x + bih + bhh
__device__ float g_h[2][SEQ * HIDN];            // 16 MB   hidden states (compact, L2-resident)
__device__ float g_feats[SEQ * 16];             // padded [t][tag]

// ---------------- helpers ----------------
__device__ __forceinline__ float4 ld_rlx4(const float4* p) {
    float4 v;
    asm volatile("ld.relaxed.gpu.global.v4.f32 {%0,%1,%2,%3}, [%4];"
                 : "=f"(v.x), "=f"(v.y), "=f"(v.z), "=f"(v.w) : "l"(p));
    return v;
}
__device__ __forceinline__ void st_rlx(float* p, float v) {
    asm volatile("st.relaxed.gpu.global.f32 [%0], %1;" :: "l"(p), "f"(v));
}
__device__ __forceinline__ u64 fma2(u64 a, u64 b, u64 c) {
    u64 d;
    asm("fma.rn.f32x2 %0, %1, %2, %3;" : "=l"(d) : "l"(a), "l"(b), "l"(c));
    return d;
}
__device__ __forceinline__ u64 add2(u64 a, u64 b) {
    u64 d;
    asm("add.rn.f32x2 %0, %1, %2;" : "=l"(d) : "l"(a), "l"(b));
    return d;
}
__device__ __forceinline__ void upk2(u64 v, float& lo, float& hi) {
    asm("mov.b64 {%0,%1}, %2;" : "=f"(lo), "=f"(hi) : "l"(v));
}
__device__ __forceinline__ float sigf(float x) {
    return __fdividef(1.0f, 1.0f + __expf(-x));
}
__device__ __forceinline__ float tanh_fast(float x) {
    return __fdividef(2.0f, 1.0f + __expf(-2.0f * x)) - 1.0f;
}

// ---------------- poison hidden-state buffer (data-as-flag protocol) --------
__global__ void poison_kernel() {
    int i = blockIdx.x * blockDim.x + threadIdx.x;   // 1M float4 = 16 MB
    float s = __uint_as_float(SENT);
    ((float4*)&g_h[0][0])[i] = make_float4(s, s, s, s);
}

// ---------------- pad Wih into g_W (zero-filled K padding) ------------------
__global__ void padw_kernel(const float* __restrict__ Wf,
                            const float* __restrict__ Wb) {
    int i = blockIdx.x * blockDim.x + threadIdx.x;
    if (i >= NGATE * EMBS) return;
    int r = i / EMBS, k = i - r * EMBS;
    g_W[0][i] = (k < INPD) ? Wf[r * INPD + k] : 0.0f;
    g_W[1][i] = (k < INPD) ? Wb[r * INPD + k] : 0.0f;
}

// ---------------- char CNN + word-embedding gather --------------------------
__global__ void embed_kernel(const int* __restrict__ sentence,
                             const int* __restrict__ chars,
                             const float* __restrict__ word_emb,
                             const float* __restrict__ char_emb,
                             const float* __restrict__ conv_w,
                             const float* __restrict__ conv_b) {
    int s = blockIdx.x;
    int tid = threadIdx.x;
    __shared__ float ce[LW][CHE];
    __shared__ float co[CHOUT][26];
    __shared__ int   cidx[LW];

    if (tid < LW) cidx[tid] = chars[s * LW + tid];
    __syncthreads();
    for (int idx = tid; idx < LW * CHE; idx += blockDim.x) {
        int r = idx / CHE, e = idx % CHE;
        ce[r][e] = char_emb[cidx[r] * CHE + e];
    }
    __syncthreads();
    for (int idx = tid; idx < CHOUT * 26; idx += blockDim.x) {
        int o = idx / 26, p = idx % 26;
        float sum = 0.0f;
        #pragma unroll
        for (int kh = 0; kh < 3; kh++) {
            int r = p - 2 + kh;
            if (r >= 0 && r < LW) {
                const float* w = conv_w + (o * 3 + kh) * CHE;
                float ss = 0.0f;
                #pragma unroll
                for (int e = 0; e < CHE; e++) ss += ce[r][e] * w[e];
                sum += ss;
            }
        }
        co[o][p] = sum;
    }
    __syncthreads();
    if (tid < CHOUT) {
        float m = -3.4e38f;
        #pragma unroll
        for (int p = 0; p < 26; p++) m = fmaxf(m, co[tid][p]);
        g_emb[s * EMBS + EMBD + tid] = m + conv_b[tid];
    }
    if (tid < EMBS - INPD) g_emb[s * EMBS + INPD + tid] = 0.0f;  // zero K pad
    int wi = sentence[s];
    const float4* src = (const float4*)(word_emb + (size_t)wi * EMBD);
    float4* dst = (float4*)(g_emb + (size_t)s * EMBS);
    for (int i = tid; i < EMBD / 4; i += blockDim.x) dst[i] = src[i];
}

// ---------------- G = emb @ Wih^T + (bih + bhh) -----------------------------
// 64x64 tile, 256 threads, 4x4 microtile, KC=16, float4 global loads from
// padded buffers (K=336, pad cols are zero so no masking needed).
__global__ __launch_bounds__(256) void gemm_kernel(
    const float* __restrict__ bihf, const float* __restrict__ bhhf,
    const float* __restrict__ bihb, const float* __restrict__ bhhb) {
    int dir = blockIdx.z;
    const float* Wp = g_W[dir];
    const float* bih = dir ? bihb : bihf;
    const float* bhh = dir ? bhhb : bhhf;
    int bm = blockIdx.y * 64;
    int bn = blockIdx.x * 64;
    int tid = threadIdx.x;
    int tx = tid & 15, ty = tid >> 4;
    int lm = tid >> 2, lk = (tid & 3) * 4;   // load map: row lm, k-offset lk

    __shared__ __align__(16) float As[16][68];
    __shared__ __align__(16) float Bs[16][68];

    float acc[4][4] = {};
    for (int k0 = 0; k0 < EMBS; k0 += 16) {
        float4 av = *(const float4*)(g_emb + (size_t)(bm + lm) * EMBS + k0 + lk);
        float4 bv = *(const float4*)(Wp + (size_t)(bn + lm) * EMBS + k0 + lk);
        As[lk + 0][lm] = av.x; As[lk + 1][lm] = av.y;
        As[lk + 2][lm] = av.z; As[lk + 3][lm] = av.w;
        Bs[lk + 0][lm] = bv.x; Bs[lk + 1][lm] = bv.y;
        Bs[lk + 2][lm] = bv.z; Bs[lk + 3][lm] = bv.w;
        __syncthreads();
        #pragma unroll
        for (int kk = 0; kk < 16; kk++) {
            float4 a = *(const float4*)&As[kk][ty * 4];
            float4 b = *(const float4*)&Bs[kk][tx * 4];
            float av4[4] = {a.x, a.y, a.z, a.w};
            float bv4[4] = {b.x, b.y, b.z, b.w};
            #pragma unroll
            for (int i = 0; i < 4; i++)
                #pragma unroll
                for (int j = 0; j < 4; j++) acc[i][j] += av4[i] * bv4[j];
        }
        __syncthreads();
    }
    float* Gp = g_G[dir];
    #pragma unroll
    for (int i = 0; i < 4; i++) {
        int t = bm + ty * 4 + i;
        #pragma unroll
        for (int j = 0; j < 4; j++) {
            int n = bn + tx * 4 + j;
            Gp[(size_t)t * NGATE + n] = acc[i][j] + bih[n] + bhh[n];
        }
    }
}

// ---------------- persistent BiLSTM recurrence -------------------------------
// Byte-exact R6 structure (best measured: 5.22ms) with ONE delta: the G
// prefetch loads use __ldcs (streaming, evict-first). G is 64MB read exactly
// once; without the hint its stream evicts the L2-resident polled h lines,
// turning some polls into 577-cyc DRAM round trips that gate every step
// (per-step time = max over 64 producer blocks).
__global__ __launch_bounds__(256, 1) void lstm_kernel(
    const float* __restrict__ Whhf, const float* __restrict__ Whhb) {
    int dir = blockIdx.x >> 6;
    int b = blockIdx.x & 63;
    int tid = threadIdx.x;
    int lr = tid >> 3;     // local gate row 0..31
    int cg = tid & 7;      // column group (64 cols each)
    int gate = lr >> 3, jj = lr & 7;
    int grow = gate * HIDN + b * 8 + jj;
    const float* Whh = dir ? Whhb : Whhf;

    // 64 weights per thread in registers for the whole sequence
    ulonglong2 wgt[16];
    {
        const ulonglong2* wsrc = (const ulonglong2*)(Whh + (size_t)grow * HIDN + cg * 64);
        #pragma unroll
        for (int q = 0; q < 16; q++) wgt[q] = wsrc[q];
    }

    __shared__ float4 hs4[8 * 17];   // swizzled h_prev
    __shared__ float  gsum[32];

    const float* Gp = g_G[dir];
    float* hp = g_h[dir];
    float cstate = 0.0f;
    float gn0 = 0.f, gn1 = 0.f, gn2 = 0.f, gn3 = 0.f;

    // prefetch G for step 0 (streaming loads: do not pollute L2)
    if (tid < 8) {
        int t0 = dir ? (SEQ - 1) : 0;
        const float* gr = Gp + (size_t)t0 * NGATE + b * 8 + tid;
        gn0 = __ldcs(gr);        gn1 = __ldcs(gr + 512);
        gn2 = __ldcs(gr + 1024); gn3 = __ldcs(gr + 1536);
    }

    for (int s = 0; s < SEQ; s++) {
        int t = dir ? (SEQ - 1 - s) : s;
        float gi = gn0, gf = gn1, gg = gn2, go = gn3;
        if (tid < 8 && s + 1 < SEQ) {
            int tn = dir ? (t - 1) : (t + 1);
            const float* gr = Gp + (size_t)tn * NGATE + b * 8 + tid;
            gn0 = __ldcs(gr);        gn1 = __ldcs(gr + 512);
            gn2 = __ldcs(gr + 1024); gn3 = __ldcs(gr + 1536);
        }

        if (s > 0) {
            int pt = dir ? (t + 1) : (t - 1);
            if (tid < 128) {
                const float4* src = (const float4*)(hp + (size_t)pt * HIDN) + tid;
                float4 v;
                do {
                    v = ld_rlx4(src);
                } while (__float_as_uint(v.x) == SENT || __float_as_uint(v.y) == SENT ||
                         __float_as_uint(v.z) == SENT || __float_as_uint(v.w) == SENT);
                hs4[(tid >> 4) * 17 + (tid & 15)] = v;
            }
        } else {
            if (tid < 136) hs4[tid] = make_float4(0.f, 0.f, 0.f, 0.f);
        }
        __syncthreads();

        // partial dot: 64 columns per thread via packed f32x2 FMAs
        const ulonglong2* hrow = (const ulonglong2*)(hs4 + cg * 17);
        u64 a0 = 0ULL, a1 = 0ULL, a2 = 0ULL, a3 = 0ULL;
        #pragma unroll
        for (int q = 0; q < 16; q += 2) {
            ulonglong2 h0 = hrow[q];
            ulonglong2 h1 = hrow[q + 1];
            a0 = fma2(wgt[q].x, h0.x, a0);
            a1 = fma2(wgt[q].y, h0.y, a1);
            a2 = fma2(wgt[q + 1].x, h1.x, a2);
            a3 = fma2(wgt[q + 1].y, h1.y, a3);
        }
        float lo, hi;
        upk2(add2(add2(a0, a1), add2(a2, a3)), lo, hi);
        float acc = lo + hi;
        acc += __shfl_xor_sync(0xffffffffu, acc, 4);
        acc += __shfl_xor_sync(0xffffffffu, acc, 2);
        acc += __shfl_xor_sync(0xffffffffu, acc, 1);
        if (cg == 0) gsum[lr] = acc;
        __syncthreads();

        // gates: single warp, lanes 0..7
        if (tid < 8) {
            float vi = sigf(gi + gsum[tid]);
            float vf = sigf(gf + gsum[8 + tid]);
            float vg = tanh_fast(gg + gsum[16 + tid]);
            float vo = sigf(go + gsum[24 + tid]);
            cstate = vf * cstate + vi * vg;
            float h = vo * tanh_fast(cstate);
            // 8 lanes, contiguous 32B: one coalesced store wavefront
            st_rlx(hp + (size_t)t * HIDN + b * 8 + tid, h);
        }
        // no trailing barrier: hs4/gsum reuse is fenced by the two barriers
        // inside the next iteration
    }
}

// ---------------- feats = [h_f ; h_b] @ h2t_w^T + h2t_b ---------------------
__global__ void feats_kernel(const float* __restrict__ h2t_w,
                             const float* __restrict__ h2t_b) {
    int t = blockIdx.x;
    int tid = threadIdx.x;
    int w = tid >> 5, lane = tid & 31;
    const float* hf = g_h[0] + (size_t)t * HIDN;
    const float* hb = g_h[1] + (size_t)t * HIDN;
    const float* wr = h2t_w + w * (2 * HIDN);
    float acc = 0.0f;
    #pragma unroll
    for (int it = 0; it < 16; it++) {
        int k = lane + it * 32;
        acc += wr[k] * hf[k];
        acc += wr[512 + k] * hb[k];
    }
    #pragma unroll
    for (int o = 16; o > 0; o >>= 1) acc += __shfl_down_sync(0xffffffffu, acc, o);
    if (lane == 0) g_feats[t * 16 + w] = acc + h2t_b[w];
}

// ---------------- Viterbi + backtrack ---------------------------------------
__global__ void viterbi_kernel(const float* __restrict__ trans,
                               float* __restrict__ out, int out_size) {
    __shared__ unsigned char bp[SEQ][NTAG];   // 45 KB
    __shared__ float fbuf[32 * 16];           // 2 KB chunk of feats
    __shared__ float fvv[NTAG];
    int tid = threadIdx.x;
    int w = tid >> 5, lane = tid & 31;

    float trow[NTAG];
    float fv = NEGV;
    if (w == 0) {
        #pragma unroll
        for (int jj = 0; jj < NTAG; jj++)
            trow[jj] = (lane < NTAG) ? trans[lane * NTAG + jj] : NEGV;
        if (lane == STARTT) fv = 0.0f;
    }

    for (int c = 0; c < SEQ / 32; c++) {
        ((float4*)fbuf)[tid] = ((const float4*)(g_feats + c * 32 * 16))[tid];
        __syncthreads();
        if (w == 0) {
            #pragma unroll 4
            for (int tt = 0; tt < 32; tt++) {
                int t = c * 32 + tt;
                float featv = (lane < NTAG) ? fbuf[tt * 16 + lane] : 0.0f;
                float best = -3.4e38f; int arg = 0;
                #pragma unroll
                for (int jj = 0; jj < NTAG; jj++) {
                    float vj = __shfl_sync(0xffffffffu, fv, jj) + trow[jj];
                    if (vj > best) { best = vj; arg = jj; }
                }
                fv = best + featv;
                if (lane < NTAG) bp[t][lane] = (unsigned char)arg;
            }
        }
        __syncthreads();
    }

    if (w == 0 && lane < NTAG) fvv[lane] = fv;
    __syncthreads();

    if (tid == 0) {
        float bestv = -3.4e38f; int bi = 0;
        #pragma unroll
        for (int i = 0; i < NTAG; i++) {
            float v = fvv[i] + trans[STOPT * NTAG + i];
            if (i == STARTT || i == STOPT) v = NEGV;
            if (v > bestv) { bestv = v; bi = i; }
        }
        if (out_size > 0) out[0] = bestv;
        int tag = bi;
        for (int t = SEQ - 1; t >= 0; t--) {
            if (1 + t < out_size) out[1 + t] = (float)tag;
            tag = bp[t][tag];
        }
    }
}

// ---------------- launch --------------------------------------------------
extern "C" void kernel_launch(void* const* d_in, const int* in_sizes, int n_in,
                              void* d_out, int out_size) {
    const int*   sentence = (const int*)d_in[0];
    const int*   chars    = (const int*)d_in[1];
    const float* word_emb = (const float*)d_in[4];
    const float* char_emb = (const float*)d_in[5];
    const float* conv_w   = (const float*)d_in[6];
    const float* conv_b   = (const float*)d_in[7];
    const float* Wih_f    = (const float*)d_in[8];
    const float* Whh_f    = (const float*)d_in[9];
    const float* bih_f    = (const float*)d_in[10];
    const float* bhh_f    = (const float*)d_in[11];
    const float* Wih_b    = (const float*)d_in[12];
    const float* Whh_b    = (const float*)d_in[13];
    const float* bih_b    = (const float*)d_in[14];
    const float* bhh_b    = (const float*)d_in[15];
    const float* h2t_w    = (const float*)d_in[16];
    const float* h2t_b    = (const float*)d_in[17];
    const float* trans    = (const float*)d_in[18];
    float* out = (float*)d_out;

    poison_kernel<<<4096, 256>>>();
    embed_kernel<<<SEQ, 128>>>(sentence, chars, word_emb, char_emb, conv_w, conv_b);
    padw_kernel<<<(NGATE * EMBS + 255) / 256, 256>>>(Wih_f, Wih_b);
    dim3 gg(NGATE / 64, SEQ / 64, 2);
    gemm_kernel<<<gg, 256>>>(bih_f, bhh_f, bih_b, bhh_b);
    lstm_kernel<<<128, 256>>>(Whh_f, Whh_b);
    feats_kernel<<<SEQ, 352>>>(h2t_w, h2t_b);
    viterbi_kernel<<<1, 128>>>(trans, out, out_size);
}